// round 14
// baseline (speedup 1.0000x reference)
#include <cuda_runtime.h>

// KVCacheHeadAttention: B=32, E=4096 -> D=128, MAX_TOKENS=2048.
// Prefix-softmax: out[b,s,:] = sum_{t<=s} e_t*v[b,t,:] / sum_{t<=s} e_t.
// R14 = R13 with qkv rebuilt: K-major (transposed) smem tiles + 4b x 4d
// register tile -> 2 LDS.128 per 16 FMA (2 B/FMA, half of R13's 4) at the
// proven 384-block grid. Score/scan/self-clean unchanged from R13.

#define BB 32
#define DD 128
#define D4 32
#define EE 4096
#define MAXT 2048
#define CHUNK 128
#define SUB 32
#define MAXSUB 64
#define QECH 64           // e-chunk per qkv block

__device__ float g_qkv[3][BB][DD];           // q,k,v (atomic-accumulated)
__device__ float g_e[BB][MAXT];              // exp(scores)
__device__ float g_cnum[BB][MAXSUB][DD];     // 32-token numerator partials
__device__ float g_cden[BB][MAXSUB];         // 32-token denominator partials
__device__ int   g_doneb[BB];                // per-b scan-finished counters

__device__ __forceinline__ float4 f4add(float4 a, float4 b) {
    return make_float4(a.x+b.x, a.y+b.y, a.z+b.z, a.w+b.w);
}
__device__ __forceinline__ float4 f4fma(float s, float4 v, float4 a) {
    return make_float4(fmaf(s,v.x,a.x), fmaf(s,v.y,a.y),
                       fmaf(s,v.z,a.z), fmaf(s,v.w,a.w));
}
__device__ __forceinline__ float4 f4scale(float4 v, float s) {
    return make_float4(v.x*s, v.y*s, v.z*s, v.w*s);
}

// ---- K1: QKV GEMM, transposed smem + 4x4 tile (grid (6,64), 256 thr) ----
// blockIdx.x: m = bx>>1, dt = bx&1 (64-d half). blockIdx.y: esp (64-wide).
// 256 threads = 2 e-halves (32 e each) x 128 tiles (4b x 4d over 32b x 64d).
// Inner loop: 2 LDS.128 -> 16 FMA. e-halves combined in smem, then 128
// threads atomicAdd 16 floats each into zero-by-contract g_qkv.
__global__ __launch_bounds__(256) void qkv_kernel(
    const float* __restrict__ x,  const float* __restrict__ Wq,
    const float* __restrict__ Wk, const float* __restrict__ Wv) {
    __shared__ float xs_t[QECH][36];   // [e][b]  9.2 KB (also reused as combine)
    __shared__ float wt[QECH][68];     // [e][d] 17.4 KB
    int m   = blockIdx.x >> 1;
    int dt  = blockIdx.x & 1;          // 64-d half
    int e0  = blockIdx.y * QECH;
    const float* W = (m == 0) ? Wq : ((m == 1) ? Wk : Wv);
    int tid = threadIdx.x;

    // x tile 32b x 64e -> xs_t[e][b] (512 float4, 2/thread, scatter STS)
    for (int i = tid; i < 512; i += 256) {
        int b = i >> 4;
        int j = (i & 15) << 2;
        float4 xv = *(const float4*)(x + (size_t)b * EE + e0 + j);
        xs_t[j + 0][b] = xv.x;
        xs_t[j + 1][b] = xv.y;
        xs_t[j + 2][b] = xv.z;
        xs_t[j + 3][b] = xv.w;
    }
    // W tile 64d x 64e -> wt[e][d] (1024 float4, 4/thread)
    for (int i = tid; i < 1024; i += 256) {
        int dl = i >> 4;
        int j  = (i & 15) << 2;
        float4 wv = __ldcs((const float4*)(W + (size_t)(dt * 64 + dl) * EE + e0 + j));
        wt[j + 0][dl] = wv.x;
        wt[j + 1][dl] = wv.y;
        wt[j + 2][dl] = wv.z;
        wt[j + 3][dl] = wv.w;
    }
    __syncthreads();

    int eg = tid >> 7;            // e-half 0/1
    int t  = tid & 127;
    int b0 = (t & 7) * 4;         // 4-b group
    int d0 = (t >> 3) * 4;        // 4-d group
    float a0x=0,a0y=0,a0z=0,a0w=0, a1x=0,a1y=0,a1z=0,a1w=0;
    float a2x=0,a2y=0,a2z=0,a2w=0, a3x=0,a3y=0,a3z=0,a3w=0;

    int eb = eg * 32;
    #pragma unroll 8
    for (int e = eb; e < eb + 32; e++) {
        float4 xv = *(float4*)&xs_t[e][b0];
        float4 wv = *(float4*)&wt[e][d0];
        a0x = fmaf(xv.x, wv.x, a0x); a0y = fmaf(xv.x, wv.y, a0y);
        a0z = fmaf(xv.x, wv.z, a0z); a0w = fmaf(xv.x, wv.w, a0w);
        a1x = fmaf(xv.y, wv.x, a1x); a1y = fmaf(xv.y, wv.y, a1y);
        a1z = fmaf(xv.y, wv.z, a1z); a1w = fmaf(xv.y, wv.w, a1w);
        a2x = fmaf(xv.z, wv.x, a2x); a2y = fmaf(xv.z, wv.y, a2y);
        a2z = fmaf(xv.z, wv.z, a2z); a2w = fmaf(xv.z, wv.w, a2w);
        a3x = fmaf(xv.w, wv.x, a3x); a3y = fmaf(xv.w, wv.y, a3y);
        a3z = fmaf(xv.w, wv.z, a3z); a3w = fmaf(xv.w, wv.w, a3w);
    }
    __syncthreads();              // all reads of xs_t done before reuse

    float* cst = &xs_t[0][0];     // combine area: 128 tiles x 16 floats
    if (eg == 1) {
        float* p = cst + t * 16;
        p[0]=a0x; p[1]=a0y; p[2]=a0z; p[3]=a0w;
        p[4]=a1x; p[5]=a1y; p[6]=a1z; p[7]=a1w;
        p[8]=a2x; p[9]=a2y; p[10]=a2z; p[11]=a2w;
        p[12]=a3x; p[13]=a3y; p[14]=a3z; p[15]=a3w;
    }
    __syncthreads();
    if (eg == 0) {
        float* p = cst + t * 16;
        int dg = dt * 64 + d0;
        atomicAdd(&g_qkv[m][b0+0][dg+0], a0x+p[0]);
        atomicAdd(&g_qkv[m][b0+0][dg+1], a0y+p[1]);
        atomicAdd(&g_qkv[m][b0+0][dg+2], a0z+p[2]);
        atomicAdd(&g_qkv[m][b0+0][dg+3], a0w+p[3]);
        atomicAdd(&g_qkv[m][b0+1][dg+0], a1x+p[4]);
        atomicAdd(&g_qkv[m][b0+1][dg+1], a1y+p[5]);
        atomicAdd(&g_qkv[m][b0+1][dg+2], a1z+p[6]);
        atomicAdd(&g_qkv[m][b0+1][dg+3], a1w+p[7]);
        atomicAdd(&g_qkv[m][b0+2][dg+0], a2x+p[8]);
        atomicAdd(&g_qkv[m][b0+2][dg+1], a2y+p[9]);
        atomicAdd(&g_qkv[m][b0+2][dg+2], a2z+p[10]);
        atomicAdd(&g_qkv[m][b0+2][dg+3], a2w+p[11]);
        atomicAdd(&g_qkv[m][b0+3][dg+0], a3x+p[12]);
        atomicAdd(&g_qkv[m][b0+3][dg+1], a3y+p[13]);
        atomicAdd(&g_qkv[m][b0+3][dg+2], a3z+p[14]);
        atomicAdd(&g_qkv[m][b0+3][dg+3], a3w+p[15]);
    }
}

// -------- K2: score + 32-token chunk partials (grid nchunks x B) ---------
__global__ __launch_bounds__(512) void score_kernel(
    const float* __restrict__ kv, const int* __restrict__ np, int max_k) {
    int b = blockIdx.y, c = blockIdx.x, tid = threadIdx.x;
    __shared__ float qs[DD], kn[DD], es[CHUNK];
    __shared__ float4 vns4[D4];
    __shared__ float4 red[4][4][D4];

    if (tid < 128) {
        qs[tid] = g_qkv[0][b][tid];
        kn[tid] = g_qkv[1][b][tid];
    } else if (tid < 160) {
        vns4[tid - 128] = *((const float4*)&g_qkv[2][b][0] + (tid - 128));
    }
    __syncthreads();

    int npos = np[b];
    int t0   = c * CHUNK;

    {
        int tok = tid >> 2, qq = tid & 3;
        int t   = t0 + tok;
        float sdot = 0.0f;
        int d0 = qq * 32;
        if (t == npos) {
            #pragma unroll
            for (int d = 0; d < 32; d++) sdot += qs[d0 + d] * kn[d0 + d];
        } else {
            const float4* krow = (const float4*)(kv + ((size_t)b * MAXT + t) * DD) + qq * 8;
            #pragma unroll
            for (int d = 0; d < 8; d++) {
                float4 kk = __ldcs(krow + d);
                sdot += qs[d0+4*d]*kk.x + qs[d0+4*d+1]*kk.y
                      + qs[d0+4*d+2]*kk.z + qs[d0+4*d+3]*kk.w;
            }
        }
        sdot += __shfl_xor_sync(0xffffffffu, sdot, 1);
        sdot += __shfl_xor_sync(0xffffffffu, sdot, 2);
        float e = (t < max_k) ? expf(sdot * 0.08838834764831845f) : 0.0f;
        if (qq == 0) {
            es[tok]   = e;
            g_e[b][t] = e;
        }
    }
    __syncthreads();

    if (tid < 128) {
        float de = es[tid];
        #pragma unroll
        for (int o = 16; o; o >>= 1) de += __shfl_xor_sync(0xffffffffu, de, o);
        if ((tid & 31) == 0) g_cden[b][c * 4 + (tid >> 5)] = de;
    }

    int sc = tid >> 7;
    int tq = (tid >> 5) & 3;
    int d4 = tid & 31;
    int tb = t0 + sc * SUB + tq * 8;
    const float4* vbase = (const float4*)(kv + (size_t)BB * MAXT * DD
                                          + ((size_t)b * MAXT + tb) * DD) + d4;
    float4 acc = make_float4(0.f, 0.f, 0.f, 0.f);
    #pragma unroll
    for (int u = 0; u < 8; u++) {
        float4 vv = vbase[(size_t)u * D4];
        if (tb + u == npos) vv = vns4[d4];
        acc = f4fma(es[sc * SUB + tq * 8 + u], vv, acc);
    }
    red[sc][tq][d4] = acc;
    __syncthreads();
    if (tid < 128) {
        int sc2 = tid >> 5, dd = tid & 31;
        float4 s0 = f4add(f4add(red[sc2][0][dd], red[sc2][1][dd]),
                          f4add(red[sc2][2][dd], red[sc2][3][dd]));
        *((float4*)&g_cnum[b][c * 4 + sc2][0] + dd) = s0;
    }
}

// --------- K3: prefix scan + output + self-clean (grid nchunks x B) ------
__global__ __launch_bounds__(512) void scan_kernel(
    const float* __restrict__ kv, const int* __restrict__ np,
    float* __restrict__ out, int max_k) {
    int b = blockIdx.y, c = blockIdx.x, tid = threadIdx.x;
    __shared__ float es[CHUNK], rden[CHUNK];
    __shared__ float4 vns4[D4];
    __shared__ float4 bred[16][D4];
    __shared__ float4 part[16][D4];
    __shared__ float warp_sums[4];
    __shared__ float denbase_s;
    __shared__ int   lastflag;

    int t0 = c * CHUNK;
    int s  = tid >> 5;
    int d4 = tid & 31;
    int tb = t0 + s * 8;

    const float4* vbase = (const float4*)(kv + (size_t)BB * MAXT * DD
                                          + ((size_t)b * MAXT + tb) * DD) + d4;
    float4 vv[8];
    #pragma unroll
    for (int u = 0; u < 8; u++) vv[u] = vbase[(size_t)u * D4];
    int npos = np[b];
    if (tid < CHUNK) es[tid] = g_e[b][t0 + tid];
    if (tid >= 480) vns4[tid - 480] = *((const float4*)&g_qkv[2][b][0] + (tid - 480));

    {
        float4 acc = make_float4(0.f, 0.f, 0.f, 0.f);
        int nrow = 4 * c;
        for (int i = s; i < nrow; i += 16)
            acc = f4add(acc, *((const float4*)&g_cnum[b][i][0] + d4));
        bred[s][d4] = acc;
    }
    if (tid < 32) {
        float db = 0.0f;
        int nrow = 4 * c;
        for (int i = tid; i < nrow; i += 32) db += g_cden[b][i];
        #pragma unroll
        for (int o = 16; o; o >>= 1) db += __shfl_xor_sync(0xffffffffu, db, o);
        if (tid == 0) denbase_s = db;
    }
    __syncthreads();

    #pragma unroll
    for (int off = 8; off; off >>= 1) {
        if (s < off) bred[s][d4] = f4add(bred[s][d4], bred[s + off][d4]);
        __syncthreads();
    }

    float dv = 0.0f;
    if (tid < 128) {
        dv = es[tid];
        int lane = tid & 31;
        #pragma unroll
        for (int o = 1; o < 32; o <<= 1) {
            float n = __shfl_up_sync(0xffffffffu, dv, o);
            if (lane >= o) dv += n;
        }
        if (lane == 31) warp_sums[tid >> 5] = dv;
    }
    __syncthreads();
    if (tid < 128) {
        int w = tid >> 5;
        float wb = denbase_s;
        for (int i = 0; i < w; i++) wb += warp_sums[i];
        rden[tid] = 1.0f / (wb + dv);
    }

    float4 vn = vns4[d4];
    float4 psum = make_float4(0.f, 0.f, 0.f, 0.f);
    #pragma unroll
    for (int u = 0; u < 8; u++) {
        if (tb + u == npos) vv[u] = vn;
        psum = f4fma(es[s * 8 + u], vv[u], psum);
    }
    part[s][d4] = psum;
    __syncthreads();

    float4 acc = bred[0][d4];
    for (int j = 0; j < s; j++) acc = f4add(acc, part[j][d4]);

    float4* obase = (float4*)(out + ((size_t)b * max_k + tb) * DD) + d4;
    #pragma unroll
    for (int u = 0; u < 8; u++) {
        acc = f4fma(es[s * 8 + u], vv[u], acc);
        if (tb + u < max_k)
            __stcs(obase + (size_t)u * D4, f4scale(acc, rden[s * 8 + u]));
    }

    __syncthreads();
    if (tid == 0)
        lastflag = (atomicAdd(&g_doneb[b], 1) == (int)gridDim.x - 1);
    __syncthreads();
    if (lastflag) {
        if (tid < 3 * DD) g_qkv[tid >> 7][b][tid & 127] = 0.0f;
        if (tid == 0)     g_doneb[b] = 0;
    }
}

// ----------------------------------------------------------------- launch
extern "C" void kernel_launch(void* const* d_in, const int* in_sizes, int n_in,
                              void* d_out, int out_size) {
    const float* x   = (const float*)d_in[0];
    const float* Wq  = (const float*)d_in[1];
    const float* Wk  = (const float*)d_in[2];
    const float* Wv  = (const float*)d_in[3];
    const float* kvc = (const float*)d_in[4];
    const int*   np  = (const int*)d_in[5];
    float* out = (float*)d_out;

    int max_k   = out_size / (BB * DD);
    int nchunks = (max_k + CHUNK - 1) / CHUNK;   // 12 for max_k=1536

    qkv_kernel<<<dim3(6, 64), 256>>>(x, Wq, Wk, Wv);
    score_kernel<<<dim3(nchunks, BB), 512>>>(kvc, np, max_k);
    scan_kernel<<<dim3(nchunks, BB), 512>>>(kvc, np, out, max_k);
}